// round 16
// baseline (speedup 1.0000x reference)
#include <cuda_runtime.h>
#include <cuda_bf16.h>
#include <cstdint>

#define NTH 512
constexpr int NH    = 100;
constexpr int NPADK = 112;
constexpr int KD    = 64;
constexpr int DIMS  = 8;
constexpr int TOT   = 512;
constexpr int WKS   = 120;
constexpr int W1KS  = 72;
constexpr int ZBS   = 72;
constexpr int W1N   = 13;
constexpr int W1PARB = 3744 * 4;
constexpr int W1PARH = 3744 * 2;

// ===== layout for body128 (TB=128) =====
constexpr int F_TB   = 128;
constexpr int F_W2S  = 0;
constexpr int F_W2T  = F_W2S + 104 * 60;
constexpr int F_W3S  = F_W2T + 104 * 60;
constexpr int F_W3T  = F_W3S + 64 * 60;
constexpr int F_W1S0 = F_W3T + 64 * 60;
constexpr int F_W1T0 = F_W1S0 + 2 * 104 * 36;
constexpr int F_HB1  = F_W1T0 + 2 * 104 * 36;
constexpr int F_HB2  = F_HB1 + F_TB * 60;
constexpr int F_ZB   = F_HB2 + F_TB * 60;
constexpr int F_LDP  = F_ZB;
constexpr int F_B1S  = F_ZB + F_TB * 36;
constexpr int F_B2S  = F_B1S + NPADK;
constexpr int F_B3S  = F_B2S + NPADK;
constexpr int F_B1T  = F_B3S + KD;
constexpr int F_B2T  = F_B1T + NPADK;
constexpr int F_B3T  = F_B2T + NPADK;
constexpr int F_SMW  = F_B3T + KD;            // 55680 w = 222720 B
constexpr int FC_S0  = F_HB2 + 0;
constexpr int FC_T0  = F_HB2 + 64;
constexpr int FC_ES0 = F_HB2 + 128;
constexpr int FC_H1S = F_HB2 + 192;
constexpr int FC_H1T = F_HB2 + 304;
constexpr int FC_H2S = F_HB2 + 416;
constexpr int FC_H2T = F_HB2 + 516;

// ===== layout for body64 (TB=64) =====
constexpr int S_TB   = 64;
constexpr int S_W2S  = 0;
constexpr int S_W2T  = S_W2S + 104 * 60;
constexpr int S_W3S  = S_W2T + 104 * 60;
constexpr int S_W3T  = S_W3S + 64 * 60;
constexpr int S_W1S0 = S_W3T + 64 * 60;
constexpr int S_W1T0 = S_W1S0 + 2 * 104 * 36;
constexpr int S_H1S  = S_W1T0 + 2 * 104 * 36;
constexpr int S_H1T  = S_H1S + S_TB * 60;
constexpr int S_H2S  = S_H1T + S_TB * 60;
constexpr int S_H2T  = S_H2S + S_TB * 60;
constexpr int S_ZB   = S_H2T + S_TB * 60;
constexpr int S_LDP  = S_ZB;
constexpr int S_B1S  = S_ZB + S_TB * 36;
constexpr int S_B2S  = S_B1S + NPADK;
constexpr int S_B3S  = S_B2S + NPADK;
constexpr int S_B1T  = S_B3S + KD;
constexpr int S_B2T  = S_B1T + NPADK;
constexpr int S_B3T  = S_B2T + NPADK;
constexpr int S_SMW  = S_B3T + KD;            // 53376 w
constexpr int SC_S0  = S_H2S + 0;
constexpr int SC_T0  = S_H2S + 64;
constexpr int SC_ES0 = S_H2S + 128;
constexpr int SC_H1S = S_H2S + 192;
constexpr int SC_H1T = S_H2S + 304;
constexpr int SC_H2S = S_H2S + 416;
constexpr int SC_H2T = S_H2S + 516;

__device__ __forceinline__ float sigm(float x) {
    float th;
    asm("tanh.approx.f32 %0, %1;" : "=f"(th) : "f"(x * 0.5f));
    return fmaf(0.5f, th, 0.5f);
}

__device__ __forceinline__ uint32_t sm_u32(const void* p) {
    uint32_t a;
    asm("{ .reg .u64 t; cvta.to.shared.u64 t, %1; cvt.u32.u64 %0, t; }" : "=r"(a) : "l"(p));
    return a;
}

__device__ __forceinline__ void bar_n(int id, int n) {
    asm volatile("bar.sync %0, %1;" :: "r"(id), "r"(n) : "memory");
}

__device__ __forceinline__ void prefetchL2(const void* p) {
    asm volatile("prefetch.global.L2 [%0];" :: "l"(p));
}

__device__ __forceinline__ void ldsm4(uint32_t a, uint32_t r[4]) {
    asm volatile("ldmatrix.sync.aligned.m8n8.x4.shared.b16 {%0,%1,%2,%3},[%4];"
                 : "=r"(r[0]), "=r"(r[1]), "=r"(r[2]), "=r"(r[3]) : "r"(a));
}
__device__ __forceinline__ void ldsm2(uint32_t a, uint32_t r[2]) {
    asm volatile("ldmatrix.sync.aligned.m8n8.x2.shared.b16 {%0,%1},[%2];"
                 : "=r"(r[0]), "=r"(r[1]) : "r"(a));
}

__device__ __forceinline__ void mma_bf(float* c, const uint32_t* a, uint32_t b0, uint32_t b1) {
    asm volatile(
        "mma.sync.aligned.m16n8k16.row.col.f32.bf16.bf16.f32 "
        "{%0,%1,%2,%3},{%4,%5,%6,%7},{%8,%9},{%0,%1,%2,%3};"
        : "+f"(c[0]), "+f"(c[1]), "+f"(c[2]), "+f"(c[3])
        : "r"(a[0]), "r"(a[1]), "r"(a[2]), "r"(a[3]), "r"(b0), "r"(b1));
}

template <int KSTEPS, int NT, int BKS>
__device__ __forceinline__ void gemm1m(uint32_t aA, uint32_t bA, uint32_t bAo,
                                       float c[][4]) {
#pragma unroll
    for (int ks = 0; ks < KSTEPS; ks++) {
        uint32_t a[4];
        ldsm4(aA, a);
#pragma unroll
        for (int p = 0; p < NT / 2; p++) {
            uint32_t b[4];
            ldsm4(bA + p * (16 * BKS * 2), b);
            mma_bf(c[2 * p],     a, b[0], b[1]);
            mma_bf(c[2 * p + 1], a, b[2], b[3]);
        }
        if constexpr (NT & 1) {
            uint32_t b[2];
            ldsm2(bAo, b);
            mma_bf(c[NT - 1], a, b[0], b[1]);
        }
        aA += 32; bA += 32; bAo += 32;
    }
}

template <int KSTEPS, int NT, int BKS>
__device__ __forceinline__ void gemm_dual(uint32_t aA,
                                          uint32_t bA1, uint32_t bAo1,
                                          uint32_t bA2, uint32_t bAo2,
                                          float c1[][4], float c2[][4]) {
#pragma unroll
    for (int ks = 0; ks < KSTEPS; ks++) {
        uint32_t a[4];
        ldsm4(aA, a);
#pragma unroll
        for (int p = 0; p < NT / 2; p++) {
            uint32_t b[4];
            ldsm4(bA1 + p * (16 * BKS * 2), b);
            mma_bf(c1[2 * p],     a, b[0], b[1]);
            mma_bf(c1[2 * p + 1], a, b[2], b[3]);
        }
        if constexpr (NT & 1) {
            uint32_t b[2];
            ldsm2(bAo1, b);
            mma_bf(c1[NT - 1], a, b[0], b[1]);
        }
#pragma unroll
        for (int p = 0; p < NT / 2; p++) {
            uint32_t b[4];
            ldsm4(bA2 + p * (16 * BKS * 2), b);
            mma_bf(c2[2 * p],     a, b[0], b[1]);
            mma_bf(c2[2 * p + 1], a, b[2], b[3]);
        }
        if constexpr (NT & 1) {
            uint32_t b[2];
            ldsm2(bAo2, b);
            mma_bf(c2[NT - 1], a, b[0], b[1]);
        }
        aA += 32; bA1 += 32; bAo1 += 32; bA2 += 32; bAo2 += 32;
    }
}

template <int NT>
__device__ __forceinline__ void store_h(const float c[][4], const float* __restrict__ bias,
                                        uint32_t* __restrict__ hb, int nb, int mrow, int g, int t) {
#pragma unroll
    for (int nt = 0; nt < NT; nt++) {
        int cc = nb + nt * 8 + 2 * t;
        float2 b = *(const float2*)&bias[cc];
#pragma unroll
        for (int h = 0; h < 2; h++) {
            int row = mrow + h * 8 + g;
            float v0 = fmaxf(c[nt][2 * h + 0] + b.x, 0.f);
            float v1 = fmaxf(c[nt][2 * h + 1] + b.y, 0.f);
            __nv_bfloat162 p = __floats2bfloat162_rn(v0, v1);
            hb[row * 60 + (cc >> 1)] = *(uint32_t*)&p;
        }
    }
}

__device__ __forceinline__ void loadW1(const float* __restrict__ Wg, float v[W1N], int tid) {
#pragma unroll
    for (int j = 0; j < W1N; j++) {
        int idx = tid + j * NTH;
        v[j] = (idx < KD * NH) ? Wg[idx] : 0.f;
    }
}
__device__ __forceinline__ void scatW1(const float v[W1N], __nv_bfloat16* __restrict__ dst, int tid) {
#pragma unroll
    for (int j = 0; j < W1N; j++) {
        int idx = tid + j * NTH;
        if (idx < KD * NH) {
            int kk = idx / NH, n = idx - kk * NH;
            dst[n * W1KS + kk] = __float2bfloat16(v[j]);
        }
    }
}

// ============================================================================
// Body 1: TB=128, 5-phase pair-barrier schedule (R13, proven)
// ============================================================================
__device__ void body128(
    float* smf, long rowBase,
    const float* __restrict__ e,
    const float* __restrict__ sW1, const float* __restrict__ sb1,
    const float* __restrict__ sW2, const float* __restrict__ sb2,
    const float* __restrict__ sW3, const float* __restrict__ sb3,
    const float* __restrict__ tW1, const float* __restrict__ tb1,
    const float* __restrict__ tW2, const float* __restrict__ tb2,
    const float* __restrict__ tW3, const float* __restrict__ tb3,
    float* __restrict__ zout, float* __restrict__ ldout)
{
    uint32_t* smu = (uint32_t*)smf;
    __nv_bfloat16* smh = (__nv_bfloat16*)smf;

    const int tid = threadIdx.x;
    const int lane = tid & 31, wid = tid >> 5;
    const int g = lane >> 2, t = lane & 3;
    const int mw = wid & 7, nw = wid >> 3;
    const int mrow = mw * 16;
    const int nb2 = nw * 56;
    const int nb3 = nw * 32;
    const int pairBar = 1 + mw;

    const float* eR0 = e    + (rowBase + mrow + g)     * TOT + nb3 + 2 * t;
    const float* eR1 = e    + (rowBase + mrow + 8 + g) * TOT + nb3 + 2 * t;
    float*       zR0 = zout + (rowBase + mrow + g)     * TOT + nb3 + 2 * t;
    float*       zR1 = zout + (rowBase + mrow + 8 + g) * TOT + nb3 + 2 * t;

    for (int w = tid; w < F_B1S; w += NTH) smu[w] = 0u;
    __syncthreads();
    for (int idx = tid; idx < NH * NH; idx += NTH) {
        int in = idx / NH, out = idx - in * NH;
        smh[F_W2S * 2 + out * WKS + in] = __float2bfloat16(sW2[idx]);
        smh[F_W2T * 2 + out * WKS + in] = __float2bfloat16(tW2[idx]);
    }
    for (int idx = tid; idx < NH * KD; idx += NTH) {
        int in = idx / KD, out = idx - in * KD;
        smh[F_W3S * 2 + out * WKS + in] = __float2bfloat16(sW3[idx]);
        smh[F_W3T * 2 + out * WKS + in] = __float2bfloat16(tW3[idx]);
    }
    for (int idx = tid; idx < NPADK; idx += NTH) {
        smf[F_B1S + idx] = (idx < NH) ? sb1[idx] : 0.f;
        smf[F_B2S + idx] = (idx < NH) ? sb2[idx] : 0.f;
        smf[F_B1T + idx] = (idx < NH) ? tb1[idx] : 0.f;
        smf[F_B2T + idx] = (idx < NH) ? tb2[idx] : 0.f;
    }
    for (int idx = tid; idx < KD; idx += NTH) {
        smf[F_B3S + idx] = sb3[idx];
        smf[F_B3T + idx] = tb3[idx];
    }

    const uint32_t smb = sm_u32(smf);
    const int aRow = lane & 15, aK = (lane >> 4) << 3;
    const uint32_t aHB1 = smb + F_HB1 * 4 + ((mrow + aRow) * WKS + aK) * 2;
    const uint32_t aHB2 = smb + F_HB2 * 4 + ((mrow + aRow) * WKS + aK) * 2;
    const uint32_t aZB  = smb + F_ZB * 4 + ((mrow + aRow) * ZBS + aK) * 2;
    const int bRow  = (lane & 7) + ((lane >> 4) << 3);
    const int bK    = ((lane >> 3) & 1) << 3;
    const int bORow = lane & 7;
    const uint32_t bW2S  = smb + F_W2S * 4 + ((nb2 + bRow) * WKS + bK) * 2;
    const uint32_t bW2So = smb + F_W2S * 4 + ((48 + bORow) * WKS + bK) * 2;
    const uint32_t bW2T  = smb + F_W2T * 4 + ((nb2 + bRow) * WKS + bK) * 2;
    const uint32_t bW2To = smb + F_W2T * 4 + ((48 + bORow) * WKS + bK) * 2;
    const uint32_t bW3S  = smb + F_W3S * 4 + ((nb3 + bRow) * WKS + bK) * 2;
    const uint32_t bW3T  = smb + F_W3T * 4 + ((nb3 + bRow) * WKS + bK) * 2;
    const uint32_t bW1S  = smb + F_W1S0 * 4 + ((nb2 + bRow) * W1KS + bK) * 2;
    const uint32_t bW1So = smb + F_W1S0 * 4 + ((48 + bORow) * W1KS + bK) * 2;
    const uint32_t bW1T  = smb + F_W1T0 * 4 + ((nb2 + bRow) * W1KS + bK) * 2;
    const uint32_t bW1To = smb + F_W1T0 * 4 + ((48 + bORow) * W1KS + bK) * 2;

    float accS[7][4], accT[7][4];
#pragma unroll
    for (int b = 0; b < 7; b++)
#pragma unroll
        for (int q = 0; q < 4; q++) { accS[b][q] = 0.f; accT[b][q] = 0.f; }
    float ldacc[2] = {0.f, 0.f};

    __syncthreads();

    // STEP 0: constant fold
    {
        if (tid < NH) {
            smf[FC_H1S + tid] = __bfloat162float(__float2bfloat16(fmaxf(smf[F_B1S + tid], 0.f)));
            smf[FC_H1T + tid] = __bfloat162float(__float2bfloat16(fmaxf(smf[F_B1T + tid], 0.f)));
        }
        __syncthreads();
        if (tid < NH) {
            float d = 0.f;
#pragma unroll 4
            for (int in = 0; in < NH; in++)
                d = fmaf(__bfloat162float(smh[F_W2S * 2 + tid * WKS + in]), smf[FC_H1S + in], d);
            smf[FC_H2S + tid] = __bfloat162float(__float2bfloat16(fmaxf(d + smf[F_B2S + tid], 0.f)));
        } else if (tid >= 256 && tid < 256 + NH) {
            int o = tid - 256;
            float d = 0.f;
#pragma unroll 4
            for (int in = 0; in < NH; in++)
                d = fmaf(__bfloat162float(smh[F_W2T * 2 + o * WKS + in]), smf[FC_H1T + in], d);
            smf[FC_H2T + o] = __bfloat162float(__float2bfloat16(fmaxf(d + smf[F_B2T + o], 0.f)));
        }
        __syncthreads();
        if (tid < KD) {
            float d = 0.f;
#pragma unroll 4
            for (int in = 0; in < NH; in++)
                d = fmaf(__bfloat162float(smh[F_W3S * 2 + tid * WKS + in]), smf[FC_H2S + in], d);
            float s = sigm(d + smf[F_B3S + tid]);
            smf[FC_S0 + tid] = s;
            smf[FC_ES0 + tid] = __expf(s);
        } else if (tid >= 256 && tid < 256 + KD) {
            int o = tid - 256;
            float d = 0.f;
#pragma unroll 4
            for (int in = 0; in < NH; in++)
                d = fmaf(__bfloat162float(smh[F_W3T * 2 + o * WKS + in]), smf[FC_H2T + in], d);
            smf[FC_T0 + o] = sigm(d + smf[F_B3T + o]);
        }
        __syncthreads();
        {
            float2 eV[8];
#pragma unroll
            for (int nt = 0; nt < 4; nt++) {
                eV[nt * 2 + 0] = __ldcs((const float2*)&eR0[nt * 8]);
                eV[nt * 2 + 1] = __ldcs((const float2*)&eR1[nt * 8]);
            }
            float partial = 0.f;
#pragma unroll
            for (int nt = 0; nt < 4; nt++) {
                int cc = nb3 + nt * 8 + 2 * t;
                float s0a = smf[FC_S0 + cc],  s0b = smf[FC_S0 + cc + 1];
                float exa = smf[FC_ES0 + cc], exb = smf[FC_ES0 + cc + 1];
                float t0a = smf[FC_T0 + cc],  t0b = smf[FC_T0 + cc + 1];
                partial += s0a + s0b;
#pragma unroll
                for (int h = 0; h < 2; h++) {
                    int row = mrow + h * 8 + g;
                    float2 e2 = eV[nt * 2 + h];
                    float z0 = exa * e2.x + t0a;
                    float z1 = exb * e2.y + t0b;
                    float* zp = (h == 0) ? (zR0 + nt * 8) : (zR1 + nt * 8);
                    __stcs((float2*)zp, make_float2(z0, z1));
                    __nv_bfloat162 zb = __floats2bfloat162_rn(z0, z1);
                    smu[F_ZB + row * 36 + (cc >> 1)] = *(uint32_t*)&zb;
                }
            }
            ldacc[0] += partial;
            ldacc[1] += partial;
            float w1v[W1N];
            loadW1(sW1, w1v, tid);
            scatW1(w1v, smh + F_W1S0 * 2, tid);
            loadW1(tW1, w1v, tid);
            scatW1(w1v, smh + F_W1T0 * 2, tid);
        }
        __syncthreads();
    }

    for (int i = 1; i < DIMS; i++) {
        const uint32_t rOff = (uint32_t)(((i + 1) & 1) * W1PARB);
        const uint32_t wHalf = (uint32_t)((i & 1) * W1PARH);

        if (nw == 0)
            gemm_dual<4, 7, W1KS>(aZB, bW1S + rOff, bW1So + rOff,
                                  bW1T + rOff, bW1To + rOff, accS, accT);
        else
            gemm_dual<4, 6, W1KS>(aZB, bW1S + rOff, 0, bW1T + rOff, 0, accS, accT);
        if (nw == 0) store_h<7>(accS, smf + F_B1S, smu + F_HB1, nb2, mrow, g, t);
        else         store_h<6>(accS, smf + F_B1S, smu + F_HB1, nb2, mrow, g, t);
        bar_n(pairBar, 64);

        if (nw == 0) {
            float D[7][4] = {};
            gemm1m<7, 7, WKS>(aHB1, bW2S, bW2So, D);
            store_h<7>(D, smf + F_B2S, smu + F_HB2, nb2, mrow, g, t);
        } else {
            float D[6][4] = {};
            gemm1m<7, 6, WKS>(aHB1, bW2S, 0, D);
            store_h<6>(D, smf + F_B2S, smu + F_HB2, nb2, mrow, g, t);
        }
        bar_n(pairBar, 64);

        float sv[4][4];
        {
            float Ds[4][4] = {};
            gemm1m<7, 4, WKS>(aHB2, bW3S, 0, Ds);
#pragma unroll
            for (int nt = 0; nt < 4; nt++) {
                int cc = nb3 + nt * 8 + 2 * t;
                float2 b3 = *(const float2*)&smf[F_B3S + cc];
#pragma unroll
                for (int h = 0; h < 2; h++) {
                    float v0 = sigm(Ds[nt][2 * h + 0] + b3.x);
                    float v1 = sigm(Ds[nt][2 * h + 1] + b3.y);
                    sv[nt][2 * h + 0] = v0;
                    sv[nt][2 * h + 1] = v1;
                    ldacc[h] += v0 + v1;
                }
            }
            if (nw == 0) store_h<7>(accT, smf + F_B1T, smu + F_HB1, nb2, mrow, g, t);
            else         store_h<6>(accT, smf + F_B1T, smu + F_HB1, nb2, mrow, g, t);
        }
        bar_n(pairBar, 64);

        {
            float w1v[W1N];
            if (i < DIMS - 1) loadW1(sW1 + (size_t)i * KD * NH, w1v, tid);
            prefetchL2(eR0 + i * KD);
            prefetchL2(eR1 + i * KD);
            if (nw == 0) {
                float D[7][4] = {};
                gemm1m<7, 7, WKS>(aHB1, bW2T, bW2To, D);
                store_h<7>(D, smf + F_B2T, smu + F_HB2, nb2, mrow, g, t);
            } else {
                float D[6][4] = {};
                gemm1m<7, 6, WKS>(aHB1, bW2T, 0, D);
                store_h<6>(D, smf + F_B2T, smu + F_HB2, nb2, mrow, g, t);
            }
            if (i < DIMS - 1) scatW1(w1v, smh + F_W1S0 * 2 + wHalf, tid);
        }
        bar_n(pairBar, 64);

        {
            const int eoff = i * KD;
            float2 eV[8];
#pragma unroll
            for (int nt = 0; nt < 4; nt++) {
                eV[nt * 2 + 0] = __ldcs((const float2*)&eR0[eoff + nt * 8]);
                eV[nt * 2 + 1] = __ldcs((const float2*)&eR1[eoff + nt * 8]);
            }

            float Dt[4][4] = {};
            gemm1m<7, 4, WKS>(aHB2, bW3T, 0, Dt);
#pragma unroll
            for (int nt = 0; nt < 4; nt++) {
                int cc = nb3 + nt * 8 + 2 * t;
                float2 b3 = *(const float2*)&smf[F_B3T + cc];
#pragma unroll
                for (int h = 0; h < 2; h++) {
                    int row = mrow + h * 8 + g;
                    float t0 = sigm(Dt[nt][2 * h + 0] + b3.x);
                    float t1 = sigm(Dt[nt][2 * h + 1] + b3.y);
                    float2 e2 = eV[nt * 2 + h];
                    float z0 = __expf(sv[nt][2 * h + 0]) * e2.x + t0;
                    float z1 = __expf(sv[nt][2 * h + 1]) * e2.y + t1;
                    float* zp = (h == 0) ? (zR0 + eoff + nt * 8) : (zR1 + eoff + nt * 8);
                    __stcs((float2*)zp, make_float2(z0, z1));
                    __nv_bfloat162 zb = __floats2bfloat162_rn(z0, z1);
                    smu[F_ZB + row * 36 + (cc >> 1)] = *(uint32_t*)&zb;
                }
            }
            if (i < DIMS - 1) {
                float w1v[W1N];
                loadW1(tW1 + (size_t)i * KD * NH, w1v, tid);
                scatW1(w1v, smh + F_W1T0 * 2 + wHalf, tid);
            }
        }
        __syncthreads();
    }

#pragma unroll
    for (int h = 0; h < 2; h++) {
        int row = mrow + h * 8 + g;
        smf[F_LDP + row * 8 + nw * 4 + t] = ldacc[h];
    }
    __syncthreads();
    if (tid < F_TB) {
        float v = 0.f;
#pragma unroll
        for (int q = 0; q < 8; q++) v += smf[F_LDP + tid * 8 + q];
        ldout[rowBase + tid] = v;
    }
}

// ============================================================================
// Body 2: TB=64, 3-phase quad-barrier schedule (R14, proven) — tail CTAs
// ============================================================================
__device__ void body64(
    float* smf, long rowBase,
    const float* __restrict__ e,
    const float* __restrict__ sW1, const float* __restrict__ sb1,
    const float* __restrict__ sW2, const float* __restrict__ sb2,
    const float* __restrict__ sW3, const float* __restrict__ sb3,
    const float* __restrict__ tW1, const float* __restrict__ tb1,
    const float* __restrict__ tW2, const float* __restrict__ tb2,
    const float* __restrict__ tW3, const float* __restrict__ tb3,
    float* __restrict__ zout, float* __restrict__ ldout)
{
    uint32_t* smu = (uint32_t*)smf;
    __nv_bfloat16* smh = (__nv_bfloat16*)smf;

    const int tid = threadIdx.x;
    const int lane = tid & 31, wid = tid >> 5;
    const int g = lane >> 2, t = lane & 3;
    const int mw = wid & 3, nq = wid >> 2;
    const int mrow = mw * 16;
    const int nb2 = (nq == 0) ? 0 : (8 + 24 * nq);
    const int nb3 = nq * 16;
    const int quadBar = 1 + mw;

    const float* eR0 = e    + (rowBase + mrow + g)     * TOT + nb3 + 2 * t;
    const float* eR1 = e    + (rowBase + mrow + 8 + g) * TOT + nb3 + 2 * t;
    float*       zR0 = zout + (rowBase + mrow + g)     * TOT + nb3 + 2 * t;
    float*       zR1 = zout + (rowBase + mrow + 8 + g) * TOT + nb3 + 2 * t;

    for (int w = tid; w < S_B1S; w += NTH) smu[w] = 0u;
    __syncthreads();
    for (int idx = tid; idx < NH * NH; idx += NTH) {
        int in = idx / NH, out = idx - in * NH;
        smh[S_W2S * 2 + out * WKS + in] = __float2bfloat16(sW2[idx]);
        smh[S_W2T * 2 + out * WKS + in] = __float2bfloat16(tW2[idx]);
    }
    for (int idx = tid; idx < NH * KD; idx += NTH) {
        int in = idx / KD, out = idx - in * KD;
        smh[S_W3S * 2 + out * WKS + in] = __float2bfloat16(sW3[idx]);
        smh[S_W3T * 2 + out * WKS + in] = __float2bfloat16(tW3[idx]);
    }
    for (int idx = tid; idx < NPADK; idx += NTH) {
        smf[S_B1S + idx] = (idx < NH) ? sb1[idx] : 0.f;
        smf[S_B2S + idx] = (idx < NH) ? sb2[idx] : 0.f;
        smf[S_B1T + idx] = (idx < NH) ? tb1[idx] : 0.f;
        smf[S_B2T + idx] = (idx < NH) ? tb2[idx] : 0.f;
    }
    for (int idx = tid; idx < KD; idx += NTH) {
        smf[S_B3S + idx] = sb3[idx];
        smf[S_B3T + idx] = tb3[idx];
    }

    const uint32_t smb = sm_u32(smf);
    const int aRow = lane & 15, aK = (lane >> 4) << 3;
    const uint32_t aH1S = smb + S_H1S * 4 + ((mrow + aRow) * WKS + aK) * 2;
    const uint32_t aH1T = smb + S_H1T * 4 + ((mrow + aRow) * WKS + aK) * 2;
    const uint32_t aH2S = smb + S_H2S * 4 + ((mrow + aRow) * WKS + aK) * 2;
    const uint32_t aH2T = smb + S_H2T * 4 + ((mrow + aRow) * WKS + aK) * 2;
    const uint32_t aZB  = smb + S_ZB * 4 + ((mrow + aRow) * ZBS + aK) * 2;
    const int bRow  = (lane & 7) + ((lane >> 4) << 3);
    const int bK    = ((lane >> 3) & 1) << 3;
    const int bORow = lane & 7;
    const uint32_t bW2S  = smb + S_W2S * 4 + ((nb2 + bRow) * WKS + bK) * 2;
    const uint32_t bW2So = smb + S_W2S * 4 + ((nb2 + 16 + bORow) * WKS + bK) * 2;
    const uint32_t bW2T  = smb + S_W2T * 4 + ((nb2 + bRow) * WKS + bK) * 2;
    const uint32_t bW2To = smb + S_W2T * 4 + ((nb2 + 16 + bORow) * WKS + bK) * 2;
    const uint32_t bW3S  = smb + S_W3S * 4 + ((nb3 + bRow) * WKS + bK) * 2;
    const uint32_t bW3T  = smb + S_W3T * 4 + ((nb3 + bRow) * WKS + bK) * 2;
    const uint32_t bW1S  = smb + S_W1S0 * 4 + ((nb2 + bRow) * W1KS + bK) * 2;
    const uint32_t bW1So = smb + S_W1S0 * 4 + ((nb2 + 16 + bORow) * W1KS + bK) * 2;
    const uint32_t bW1T  = smb + S_W1T0 * 4 + ((nb2 + bRow) * W1KS + bK) * 2;
    const uint32_t bW1To = smb + S_W1T0 * 4 + ((nb2 + 16 + bORow) * W1KS + bK) * 2;

    float accS[4][4], accT[4][4];
#pragma unroll
    for (int b = 0; b < 4; b++)
#pragma unroll
        for (int q = 0; q < 4; q++) { accS[b][q] = 0.f; accT[b][q] = 0.f; }
    float ldacc[2] = {0.f, 0.f};

    __syncthreads();

    // STEP 0: constant fold
    {
        if (tid < NH) {
            smf[SC_H1S + tid] = __bfloat162float(__float2bfloat16(fmaxf(smf[S_B1S + tid], 0.f)));
            smf[SC_H1T + tid] = __bfloat162float(__float2bfloat16(fmaxf(smf[S_B1T + tid], 0.f)));
        }
        __syncthreads();
        if (tid < NH) {
            float d = 0.f;
#pragma unroll 4
            for (int in = 0; in < NH; in++)
                d = fmaf(__bfloat162float(smh[S_W2S * 2 + tid * WKS + in]), smf[SC_H1S + in], d);
            smf[SC_H2S + tid] = __bfloat162float(__float2bfloat16(fmaxf(d + smf[S_B2S + tid], 0.f)));
        } else if (tid >= 256 && tid < 256 + NH) {
            int o = tid - 256;
            float d = 0.f;
#pragma unroll 4
            for (int in = 0; in < NH; in++)
                d = fmaf(__bfloat162float(smh[S_W2T * 2 + o * WKS + in]), smf[SC_H1T + in], d);
            smf[SC_H2T + o] = __bfloat162float(__float2bfloat16(fmaxf(d + smf[S_B2T + o], 0.f)));
        }
        __syncthreads();
        if (tid < KD) {
            float d = 0.f;
#pragma unroll 4
            for (int in = 0; in < NH; in++)
                d = fmaf(__bfloat162float(smh[S_W3S * 2 + tid * WKS + in]), smf[SC_H2S + in], d);
            float s = sigm(d + smf[S_B3S + tid]);
            smf[SC_S0 + tid] = s;
            smf[SC_ES0 + tid] = __expf(s);
        } else if (tid >= 256 && tid < 256 + KD) {
            int o = tid - 256;
            float d = 0.f;
#pragma unroll 4
            for (int in = 0; in < NH; in++)
                d = fmaf(__bfloat162float(smh[S_W3T * 2 + o * WKS + in]), smf[SC_H2T + in], d);
            smf[SC_T0 + o] = sigm(d + smf[S_B3T + o]);
        }
        __syncthreads();
        {
            float2 eV[4];
#pragma unroll
            for (int nt = 0; nt < 2; nt++) {
                eV[nt * 2 + 0] = __ldcs((const float2*)&eR0[nt * 8]);
                eV[nt * 2 + 1] = __ldcs((const float2*)&eR1[nt * 8]);
            }
            float partial = 0.f;
#pragma unroll
            for (int nt = 0; nt < 2; nt++) {
                int cc = nb3 + nt * 8 + 2 * t;
                float s0a = smf[SC_S0 + cc],  s0b = smf[SC_S0 + cc + 1];
                float exa = smf[SC_ES0 + cc], exb = smf[SC_ES0 + cc + 1];
                float t0a = smf[SC_T0 + cc],  t0b = smf[SC_T0 + cc + 1];
                partial += s0a + s0b;
#pragma unroll
                for (int h = 0; h < 2; h++) {
                    int row = mrow + h * 8 + g;
                    float2 e2 = eV[nt * 2 + h];
                    float z0 = exa * e2.x + t0a;
                    float z1 = exb * e2.y + t0b;
                    float* zp = (h == 0) ? (zR0 + nt * 8) : (zR1 + nt * 8);
                    __stcs((float2*)zp, make_float2(z0, z1));
                    __nv_bfloat162 zb = __floats2bfloat162_rn(z0, z1);
                    smu[S_ZB + row * 36 + (cc >> 1)] = *(uint32_t*)&zb;
                }
            }
            ldacc[0] += partial;
            ldacc[1] += partial;
            float w1v[W1N];
            loadW1(sW1, w1v, tid);
            scatW1(w1v, smh + S_W1S0 * 2, tid);
            loadW1(tW1, w1v, tid);
            scatW1(w1v, smh + S_W1T0 * 2, tid);
        }
        __syncthreads();
    }

    for (int i = 1; i < DIMS; i++) {
        const uint32_t rOff = (uint32_t)(((i + 1) & 1) * W1PARB);
        const uint32_t wHalf = (uint32_t)((i & 1) * W1PARH);

        if (nq == 0) {
            gemm_dual<4, 4, W1KS>(aZB, bW1S + rOff, 0, bW1T + rOff, 0, accS, accT);
            store_h<4>(accS, smf + S_B1S, smu + S_H1S, nb2, mrow, g, t);
            store_h<4>(accT, smf + S_B1T, smu + S_H1T, nb2, mrow, g, t);
        } else {
            gemm_dual<4, 3, W1KS>(aZB, bW1S + rOff, bW1So + rOff,
                                  bW1T + rOff, bW1To + rOff, accS, accT);
            store_h<3>(accS, smf + S_B1S, smu + S_H1S, nb2, mrow, g, t);
            store_h<3>(accT, smf + S_B1T, smu + S_H1T, nb2, mrow, g, t);
        }
        bar_n(quadBar, 128);

        {
            float w1v[W1N];
            if (i < DIMS - 1) loadW1(sW1 + (size_t)i * KD * NH, w1v, tid);
            prefetchL2(eR0 + i * KD);
            prefetchL2(eR1 + i * KD);
            if (nq == 0) {
                float D[4][4] = {};
                gemm1m<7, 4, WKS>(aH1S, bW2S, 0, D);
                store_h<4>(D, smf + S_B2S, smu + S_H2S, nb2, mrow, g, t);
                float D2[4][4] = {};
                gemm1m<7, 4, WKS>(aH1T, bW2T, 0, D2);
                store_h<4>(D2, smf + S_B2T, smu + S_H2T, nb2, mrow, g, t);
            } else {
                float D[3][4] = {};
                gemm1m<7, 3, WKS>(aH1S, bW2S, bW2So, D);
                store_h<3>(D, smf + S_B2S, smu + S_H2S, nb2, mrow, g, t);
                float D2[3][4] = {};
                gemm1m<7, 3, WKS>(aH1T, bW2T, bW2To, D2);
                store_h<3>(D2, smf + S_B2T, smu + S_H2T, nb2, mrow, g, t);
            }
            if (i < DIMS - 1) scatW1(w1v, smh + S_W1S0 * 2 + wHalf, tid);
        }
        bar_n(quadBar, 128);

        {
            float w1t[W1N];
            if (i < DIMS - 1) loadW1(tW1 + (size_t)i * KD * NH, w1t, tid);

            const int eoff = i * KD;
            float2 eV[4];
#pragma unroll
            for (int nt = 0; nt < 2; nt++) {
                eV[nt * 2 + 0] = __ldcs((const float2*)&eR0[eoff + nt * 8]);
                eV[nt * 2 + 1] = __ldcs((const float2*)&eR1[eoff + nt * 8]);
            }

            float Ds[2][4] = {};
            gemm1m<7, 2, WKS>(aH2S, bW3S, 0, Ds);
            float sv[2][4];
#pragma unroll
            for (int nt = 0; nt < 2; nt++) {
                int cc = nb3 + nt * 8 + 2 * t;
                float2 b3 = *(const float2*)&smf[S_B3S + cc];
#pragma unroll
                for (int h = 0; h < 2; h++) {
                    float v0 = sigm(Ds[nt][2 * h + 0] + b3.x);
                    float v1 = sigm(Ds[nt][2 * h + 1] + b3.y);
                    sv[nt][2 * h + 0] = v0;
                    sv[nt][2 * h + 1] = v1;
                    ldacc[h] += v0 + v1;
                }
            }

            float Dt[2][4] = {};
            gemm1m<7, 2, WKS>(aH2T, bW3T, 0, Dt);
#pragma unroll
            for (int nt = 0; nt < 2; nt++) {
                int cc = nb3 + nt * 8 + 2 * t;
                float2 b3 = *(const float2*)&smf[S_B3T + cc];
#pragma unroll
                for (int h = 0; h < 2; h++) {
                    int row = mrow + h * 8 + g;
                    float t0 = sigm(Dt[nt][2 * h + 0] + b3.x);
                    float t1 = sigm(Dt[nt][2 * h + 1] + b3.y);
                    float2 e2 = eV[nt * 2 + h];
                    float z0 = __expf(sv[nt][2 * h + 0]) * e2.x + t0;
                    float z1 = __expf(sv[nt][2 * h + 1]) * e2.y + t1;
                    float* zp = (h == 0) ? (zR0 + eoff + nt * 8) : (zR1 + eoff + nt * 8);
                    __stcs((float2*)zp, make_float2(z0, z1));
                    if (i < DIMS - 1) {
                        __nv_bfloat162 zb = __floats2bfloat162_rn(z0, z1);
                        smu[S_ZB + row * 36 + (cc >> 1)] = *(uint32_t*)&zb;
                    }
                }
            }
            if (i < DIMS - 1) scatW1(w1t, smh + S_W1T0 * 2 + wHalf, tid);
        }
        __syncthreads();
    }

#pragma unroll
    for (int h = 0; h < 2; h++) {
        int row = mrow + h * 8 + g;
        smf[S_LDP + row * 16 + nq * 4 + t] = ldacc[h];
    }
    __syncthreads();
    if (tid < S_TB) {
        float v = 0.f;
#pragma unroll
        for (int q = 0; q < 16; q++) v += smf[S_LDP + tid * 16 + q];
        ldout[rowBase + tid] = v;
    }
}

// ============================================================================
// Heterogeneous dispatch: blocks [0,n1) run TB=128 body; rest run TB=64 body.
// Single grid -> tail CTAs are work-stolen onto SMs as they free, absorbing
// the big-wave finish spread instead of barriering on it.
// ============================================================================
__global__ void __launch_bounds__(NTH, 1) flow_hetero(
    const float* __restrict__ e,
    const float* __restrict__ sW1, const float* __restrict__ sb1,
    const float* __restrict__ sW2, const float* __restrict__ sb2,
    const float* __restrict__ sW3, const float* __restrict__ sb3,
    const float* __restrict__ tW1, const float* __restrict__ tb1,
    const float* __restrict__ tW2, const float* __restrict__ tb2,
    const float* __restrict__ tW3, const float* __restrict__ tb3,
    float* __restrict__ zout, float* __restrict__ ldout, int n1)
{
    extern __shared__ float smf[];
    const int bid = blockIdx.x;
    if (bid < n1) {
        body128(smf, (long)bid * F_TB,
                e, sW1, sb1, sW2, sb2, sW3, sb3,
                tW1, tb1, tW2, tb2, tW3, tb3, zout, ldout);
    } else {
        long rowBase = (long)n1 * F_TB + (long)(bid - n1) * S_TB;
        body64(smf, rowBase,
               e, sW1, sb1, sW2, sb2, sW3, sb3,
               tW1, tb1, tW2, tb2, tW3, tb3, zout, ldout);
    }
}

extern "C" void kernel_launch(void* const* d_in, const int* in_sizes, int n_in,
                              void* d_out, int out_size) {
    const float* e   = (const float*)d_in[0];
    // d_in[1] = C (strictly upper-triangular DAG -> incremental layer-1 acc is exact)
    const float* sW1 = (const float*)d_in[2];
    const float* sb1 = (const float*)d_in[3];
    const float* sW2 = (const float*)d_in[4];
    const float* sb2 = (const float*)d_in[5];
    const float* sW3 = (const float*)d_in[6];
    const float* sb3 = (const float*)d_in[7];
    const float* tW1 = (const float*)d_in[8];
    const float* tb1 = (const float*)d_in[9];
    const float* tW2 = (const float*)d_in[10];
    const float* tb2 = (const float*)d_in[11];
    const float* tW3 = (const float*)d_in[12];
    const float* tb3 = (const float*)d_in[13];

    float* out = (float*)d_out;
    const int B = in_sizes[0] / TOT;
    float* zout  = out;
    float* ldout = out + (size_t)B * TOT;

    const int SMS = 148;
    int tiles128 = B / 128;
    int n1 = (tiles128 / SMS) * SMS;          // whole 148-CTA waves of TB=128
    long rows1 = (long)n1 * 128;
    long rem = (long)B - rows1;
    int n2 = (int)(rem / 64);
    if (rem % 64 != 0) { n1 = tiles128; rows1 = (long)n1 * 128; n2 = 0; }

    cudaFuncSetAttribute(flow_hetero, cudaFuncAttributeMaxDynamicSharedMemorySize,
                         F_SMW * (int)sizeof(float));

    flow_hetero<<<n1 + n2, NTH, F_SMW * sizeof(float)>>>(
        e, sW1, sb1, sW2, sb2, sW3, sb3,
        tW1, tb1, tW2, tb2, tW3, tb3,
        zout, ldout, n1);
}

// round 17
// speedup vs baseline: 1.1423x; 1.1423x over previous
#include <cuda_runtime.h>
#include <cuda_bf16.h>
#include <cstdint>

#define NTH 512
constexpr int NH    = 100;
constexpr int NPADK = 112;
constexpr int KD    = 64;
constexpr int DIMS  = 8;
constexpr int TOT   = 512;
constexpr int WKS   = 120;
constexpr int W1KS  = 72;
constexpr int ZBS   = 72;

// ===== static smem image layout (shared by both bodies) =====
constexpr int F_W2S  = 0;                      // [104][60w]
constexpr int F_W2T  = F_W2S + 104 * 60;       // 6240
constexpr int F_W3S  = F_W2T + 104 * 60;       // 12480 [64][60w]
constexpr int F_W3T  = F_W3S + 64 * 60;        // 16320
constexpr int F_W1S0 = F_W3T + 64 * 60;        // 20160 [104][36w] x2 parity
constexpr int F_W1T0 = F_W1S0 + 2 * 104 * 36;  // 27648
constexpr int STATIC_W = F_W1T0 + 2 * 104 * 36; // 35136 words
constexpr int SLICE_W  = 104 * 36;              // 3744 words per W1 slice image
constexpr int SLICE_V  = SLICE_W / 4;           // 936 uint4

// ===== body128 (TB=128) dynamic layout =====
constexpr int F_TB   = 128;
constexpr int F_HB1  = STATIC_W;               // 35136 [128][60w]
constexpr int F_HB2  = F_HB1 + F_TB * 60;      // 42816
constexpr int F_ZB   = F_HB2 + F_TB * 60;      // 50496 [128][36w]
constexpr int F_LDP  = F_ZB;
constexpr int F_B1S  = F_ZB + F_TB * 36;       // 55104
constexpr int F_B2S  = F_B1S + NPADK;
constexpr int F_B3S  = F_B2S + NPADK;
constexpr int F_B1T  = F_B3S + KD;
constexpr int F_B2T  = F_B1T + NPADK;
constexpr int F_B3T  = F_B2T + NPADK;
constexpr int F_SMW  = F_B3T + KD;             // 55680 w = 222720 B
constexpr int FC_S0  = F_HB2 + 0;              // constants live in HB2 (free at step 0)

// ===== body64 (TB=64) dynamic layout =====
constexpr int S_TB   = 64;
constexpr int S_H1S  = STATIC_W;               // 35136 [64][60w]
constexpr int S_H1T  = S_H1S + S_TB * 60;
constexpr int S_H2S  = S_H1T + S_TB * 60;
constexpr int S_H2T  = S_H2S + S_TB * 60;
constexpr int S_ZB   = S_H2T + S_TB * 60;      // [64][36w]
constexpr int S_LDP  = S_ZB;
constexpr int S_B1S  = S_ZB + S_TB * 36;       // 52800
constexpr int S_B2S  = S_B1S + NPADK;
constexpr int S_B3S  = S_B2S + NPADK;
constexpr int S_B1T  = S_B3S + KD;
constexpr int S_B2T  = S_B1T + NPADK;
constexpr int S_B3T  = S_B2T + NPADK;
constexpr int S_SMW  = S_B3T + KD;
constexpr int SC_S0  = S_H2S + 0;

// ===== global scratch =====
constexpr int GS_W1    = STATIC_W;             // 14 slice images (s 0..6, t 0..6)
constexpr int GS_CONST = GS_W1 + 14 * SLICE_W; // 87552: s0[64], t0[64], es0[64]
constexpr int GS_TOTAL = GS_CONST + 192;       // 87744 words (351 KB)
__device__ __align__(16) float g_scratch[GS_TOTAL];

__device__ __forceinline__ float sigm(float x) {
    float th;
    asm("tanh.approx.f32 %0, %1;" : "=f"(th) : "f"(x * 0.5f));
    return fmaf(0.5f, th, 0.5f);
}
__device__ __forceinline__ float bf16r(float x) {
    return __bfloat162float(__float2bfloat16(x));
}
__device__ __forceinline__ uint32_t pack2(float a, float b) {
    __nv_bfloat162 p = __floats2bfloat162_rn(a, b);
    return *(uint32_t*)&p;
}

__device__ __forceinline__ uint32_t sm_u32(const void* p) {
    uint32_t a;
    asm("{ .reg .u64 t; cvta.to.shared.u64 t, %1; cvt.u32.u64 %0, t; }" : "=r"(a) : "l"(p));
    return a;
}
__device__ __forceinline__ void bar_n(int id, int n) {
    asm volatile("bar.sync %0, %1;" :: "r"(id), "r"(n) : "memory");
}
__device__ __forceinline__ void prefetchL2(const void* p) {
    asm volatile("prefetch.global.L2 [%0];" :: "l"(p));
}
__device__ __forceinline__ void ldsm4(uint32_t a, uint32_t r[4]) {
    asm volatile("ldmatrix.sync.aligned.m8n8.x4.shared.b16 {%0,%1,%2,%3},[%4];"
                 : "=r"(r[0]), "=r"(r[1]), "=r"(r[2]), "=r"(r[3]) : "r"(a));
}
__device__ __forceinline__ void ldsm2(uint32_t a, uint32_t r[2]) {
    asm volatile("ldmatrix.sync.aligned.m8n8.x2.shared.b16 {%0,%1},[%2];"
                 : "=r"(r[0]), "=r"(r[1]) : "r"(a));
}
__device__ __forceinline__ void mma_bf(float* c, const uint32_t* a, uint32_t b0, uint32_t b1) {
    asm volatile(
        "mma.sync.aligned.m16n8k16.row.col.f32.bf16.bf16.f32 "
        "{%0,%1,%2,%3},{%4,%5,%6,%7},{%8,%9},{%0,%1,%2,%3};"
        : "+f"(c[0]), "+f"(c[1]), "+f"(c[2]), "+f"(c[3])
        : "r"(a[0]), "r"(a[1]), "r"(a[2]), "r"(a[3]), "r"(b0), "r"(b1));
}

template <int KSTEPS, int NT, int BKS>
__device__ __forceinline__ void gemm1m(uint32_t aA, uint32_t bA, uint32_t bAo, float c[][4]) {
#pragma unroll
    for (int ks = 0; ks < KSTEPS; ks++) {
        uint32_t a[4];
        ldsm4(aA, a);
#pragma unroll
        for (int p = 0; p < NT / 2; p++) {
            uint32_t b[4];
            ldsm4(bA + p * (16 * BKS * 2), b);
            mma_bf(c[2 * p],     a, b[0], b[1]);
            mma_bf(c[2 * p + 1], a, b[2], b[3]);
        }
        if constexpr (NT & 1) {
            uint32_t b[2];
            ldsm2(bAo, b);
            mma_bf(c[NT - 1], a, b[0], b[1]);
        }
        aA += 32; bA += 32; bAo += 32;
    }
}

template <int KSTEPS, int NT, int BKS>
__device__ __forceinline__ void gemm_dual(uint32_t aA,
                                          uint32_t bA1, uint32_t bAo1,
                                          uint32_t bA2, uint32_t bAo2,
                                          float c1[][4], float c2[][4]) {
#pragma unroll
    for (int ks = 0; ks < KSTEPS; ks++) {
        uint32_t a[4];
        ldsm4(aA, a);
#pragma unroll
        for (int p = 0; p < NT / 2; p++) {
            uint32_t b[4];
            ldsm4(bA1 + p * (16 * BKS * 2), b);
            mma_bf(c1[2 * p],     a, b[0], b[1]);
            mma_bf(c1[2 * p + 1], a, b[2], b[3]);
        }
        if constexpr (NT & 1) {
            uint32_t b[2];
            ldsm2(bAo1, b);
            mma_bf(c1[NT - 1], a, b[0], b[1]);
        }
#pragma unroll
        for (int p = 0; p < NT / 2; p++) {
            uint32_t b[4];
            ldsm4(bA2 + p * (16 * BKS * 2), b);
            mma_bf(c2[2 * p],     a, b[0], b[1]);
            mma_bf(c2[2 * p + 1], a, b[2], b[3]);
        }
        if constexpr (NT & 1) {
            uint32_t b[2];
            ldsm2(bAo2, b);
            mma_bf(c2[NT - 1], a, b[0], b[1]);
        }
        aA += 32; bA1 += 32; bAo1 += 32; bA2 += 32; bAo2 += 32;
    }
}

template <int NT>
__device__ __forceinline__ void store_h(const float c[][4], const float* __restrict__ bias,
                                        uint32_t* __restrict__ hb, int nb, int mrow, int g, int t) {
#pragma unroll
    for (int nt = 0; nt < NT; nt++) {
        int cc = nb + nt * 8 + 2 * t;
        float2 b = *(const float2*)&bias[cc];
#pragma unroll
        for (int h = 0; h < 2; h++) {
            int row = mrow + h * 8 + g;
            float v0 = fmaxf(c[nt][2 * h + 0] + b.x, 0.f);
            float v1 = fmaxf(c[nt][2 * h + 1] + b.y, 0.f);
            __nv_bfloat162 p = __floats2bfloat162_rn(v0, v1);
            hb[row * 60 + (cc >> 1)] = *(uint32_t*)&p;
        }
    }
}

// W1 slice staging: pre-transposed bf16 image copy (load early, store late)
__device__ __forceinline__ void loadSlice(const uint4* __restrict__ src, uint4 v[2], int tid) {
    v[0] = src[tid];
    if (tid + NTH < SLICE_V) v[1] = src[tid + NTH];
}
__device__ __forceinline__ void storeSlice(uint4* __restrict__ dst, const uint4 v[2], int tid) {
    dst[tid] = v[0];
    if (tid + NTH < SLICE_V) dst[tid + NTH] = v[1];
}

// ============================================================================
// Init kernel: build static smem image, W1 slice images, step-0 constants.
// Bit-identical conversions to the previous per-CTA code.
// ============================================================================
__global__ void init_scratch(
    const float* __restrict__ sW1, const float* __restrict__ sb1,
    const float* __restrict__ sW2, const float* __restrict__ sb2,
    const float* __restrict__ sW3, const float* __restrict__ sb3,
    const float* __restrict__ tW1, const float* __restrict__ tb1,
    const float* __restrict__ tW2, const float* __restrict__ tb2,
    const float* __restrict__ tW3, const float* __restrict__ tb3)
{
    uint32_t* gs = (uint32_t*)g_scratch;
    if (blockIdx.x < 32) {
        for (int idx = blockIdx.x * blockDim.x + threadIdx.x; idx < GS_CONST;
             idx += 32 * blockDim.x) {
            uint32_t val = 0u;
            if (idx < F_W2T) {                         // W2S [out 104][in 60w]
                int r = idx / 60, q = (idx - r * 60) * 2;
                float a = (r < NH && q     < NH) ? sW2[q * NH + r]       : 0.f;
                float b = (r < NH && q + 1 < NH) ? sW2[(q + 1) * NH + r] : 0.f;
                val = pack2(a, b);
            } else if (idx < F_W3S) {                  // W2T
                int l = idx - F_W2T;
                int r = l / 60, q = (l - r * 60) * 2;
                float a = (r < NH && q     < NH) ? tW2[q * NH + r]       : 0.f;
                float b = (r < NH && q + 1 < NH) ? tW2[(q + 1) * NH + r] : 0.f;
                val = pack2(a, b);
            } else if (idx < F_W3T) {                  // W3S [out 64][in 60w]
                int l = idx - F_W3S;
                int r = l / 60, q = (l - r * 60) * 2;
                float a = (q     < NH) ? sW3[q * KD + r]       : 0.f;
                float b = (q + 1 < NH) ? sW3[(q + 1) * KD + r] : 0.f;
                val = pack2(a, b);
            } else if (idx < F_W1S0) {                 // W3T
                int l = idx - F_W3T;
                int r = l / 60, q = (l - r * 60) * 2;
                float a = (q     < NH) ? tW3[q * KD + r]       : 0.f;
                float b = (q + 1 < NH) ? tW3[(q + 1) * KD + r] : 0.f;
                val = pack2(a, b);
            } else if (idx < F_W1T0) {                 // W1S0: parity0 = s slice0, parity1 = 0
                int l = idx - F_W1S0;
                if (l < SLICE_W) {
                    int n = l / 36, kk = (l - n * 36) * 2;
                    float a = (n < NH && kk     < KD) ? sW1[kk * NH + n]       : 0.f;
                    float b = (n < NH && kk + 1 < KD) ? sW1[(kk + 1) * NH + n] : 0.f;
                    val = pack2(a, b);
                }
            } else if (idx < STATIC_W) {               // W1T0: parity0 = t slice0, parity1 = 0
                int l = idx - F_W1T0;
                if (l < SLICE_W) {
                    int n = l / 36, kk = (l - n * 36) * 2;
                    float a = (n < NH && kk     < KD) ? tW1[kk * NH + n]       : 0.f;
                    float b = (n < NH && kk + 1 < KD) ? tW1[(kk + 1) * NH + n] : 0.f;
                    val = pack2(a, b);
                }
            } else {                                   // GS_W1: s slices 0..6, then t 0..6
                int l = idx - GS_W1;
                int sl = l / SLICE_W;
                int li = l - sl * SLICE_W;
                const float* W = (sl < 7) ? (sW1 + (size_t)sl * KD * NH)
                                          : (tW1 + (size_t)(sl - 7) * KD * NH);
                int n = li / 36, kk = (li - n * 36) * 2;
                float a = (n < NH && kk     < KD) ? W[kk * NH + n]       : 0.f;
                float b = (n < NH && kk + 1 < KD) ? W[(kk + 1) * NH + n] : 0.f;
                val = pack2(a, b);
            }
            gs[idx] = val;
        }
    } else {
        // step-0 constants (block 32; inputs identically zero -> batch-constant)
        __shared__ float sh[512];
        float* h1s = sh;       float* h1t = sh + 128;
        float* h2s = sh + 256; float* h2t = sh + 384;
        int tid = threadIdx.x;
        if (tid < NH) {
            h1s[tid] = bf16r(fmaxf(sb1[tid], 0.f));
            h1t[tid] = bf16r(fmaxf(tb1[tid], 0.f));
        }
        __syncthreads();
        if (tid < NH) {
            float d = 0.f;
#pragma unroll 4
            for (int in = 0; in < NH; in++)
                d = fmaf(bf16r(sW2[in * NH + tid]), h1s[in], d);
            h2s[tid] = bf16r(fmaxf(d + sb2[tid], 0.f));
        } else if (tid >= 128 && tid < 128 + NH) {
            int o = tid - 128;
            float d = 0.f;
#pragma unroll 4
            for (int in = 0; in < NH; in++)
                d = fmaf(bf16r(tW2[in * NH + o]), h1t[in], d);
            h2t[o] = bf16r(fmaxf(d + tb2[o], 0.f));
        }
        __syncthreads();
        if (tid < KD) {
            float d = 0.f;
#pragma unroll 4
            for (int in = 0; in < NH; in++)
                d = fmaf(bf16r(sW3[in * KD + tid]), h2s[in], d);
            float s = sigm(d + sb3[tid]);
            g_scratch[GS_CONST + tid] = s;            // s0
            g_scratch[GS_CONST + 128 + tid] = __expf(s);  // es0
        } else if (tid >= 128 && tid < 128 + KD) {
            int o = tid - 128;
            float d = 0.f;
#pragma unroll 4
            for (int in = 0; in < NH; in++)
                d = fmaf(bf16r(tW3[in * KD + o]), h2t[in], d);
            g_scratch[GS_CONST + 64 + o] = sigm(d + tb3[o]);  // t0
        }
    }
}

// ============================================================================
// Body 1: TB=128, 5-phase pair-barrier schedule
// ============================================================================
__device__ void body128(
    float* smf, long rowBase,
    const float* __restrict__ e,
    const float* __restrict__ sb1, const float* __restrict__ sb2, const float* __restrict__ sb3,
    const float* __restrict__ tb1, const float* __restrict__ tb2, const float* __restrict__ tb3,
    float* __restrict__ zout, float* __restrict__ ldout)
{
    uint32_t* smu = (uint32_t*)smf;

    const int tid = threadIdx.x;
    const int lane = tid & 31, wid = tid >> 5;
    const int g = lane >> 2, t = lane & 3;
    const int mw = wid & 7, nw = wid >> 3;
    const int mrow = mw * 16;
    const int nb2 = nw * 56;
    const int nb3 = nw * 32;
    const int pairBar = 1 + mw;

    const float* eR0 = e    + (rowBase + mrow + g)     * TOT + nb3 + 2 * t;
    const float* eR1 = e    + (rowBase + mrow + 8 + g) * TOT + nb3 + 2 * t;
    float*       zR0 = zout + (rowBase + mrow + g)     * TOT + nb3 + 2 * t;
    float*       zR1 = zout + (rowBase + mrow + 8 + g) * TOT + nb3 + 2 * t;

    // ---- prologue: copy static image; zero dynamic region; biases ----
    {
        const uint4* gsv = (const uint4*)g_scratch;
        uint4* smv = (uint4*)smf;
        for (int w = tid; w < STATIC_W / 4; w += NTH) smv[w] = gsv[w];
        const uint4 z4 = make_uint4(0, 0, 0, 0);
        for (int w = tid; w < (F_B1S - F_HB1) / 4; w += NTH) smv[STATIC_W / 4 + w] = z4;
    }
    for (int idx = tid; idx < NPADK; idx += NTH) {
        smf[F_B1S + idx] = (idx < NH) ? sb1[idx] : 0.f;
        smf[F_B2S + idx] = (idx < NH) ? sb2[idx] : 0.f;
        smf[F_B1T + idx] = (idx < NH) ? tb1[idx] : 0.f;
        smf[F_B2T + idx] = (idx < NH) ? tb2[idx] : 0.f;
    }
    for (int idx = tid; idx < KD; idx += NTH) {
        smf[F_B3S + idx] = sb3[idx];
        smf[F_B3T + idx] = tb3[idx];
    }
    __syncthreads();
    if (tid < 192) smf[FC_S0 + tid] = g_scratch[GS_CONST + tid];  // s0|t0|es0

    const uint32_t smb = sm_u32(smf);
    const int aRow = lane & 15, aK = (lane >> 4) << 3;
    const uint32_t aHB1 = smb + F_HB1 * 4 + ((mrow + aRow) * WKS + aK) * 2;
    const uint32_t aHB2 = smb + F_HB2 * 4 + ((mrow + aRow) * WKS + aK) * 2;
    const uint32_t aZB  = smb + F_ZB * 4 + ((mrow + aRow) * ZBS + aK) * 2;
    const int bRow  = (lane & 7) + ((lane >> 4) << 3);
    const int bK    = ((lane >> 3) & 1) << 3;
    const int bORow = lane & 7;
    const uint32_t bW2S  = smb + F_W2S * 4 + ((nb2 + bRow) * WKS + bK) * 2;
    const uint32_t bW2So = smb + F_W2S * 4 + ((48 + bORow) * WKS + bK) * 2;
    const uint32_t bW2T  = smb + F_W2T * 4 + ((nb2 + bRow) * WKS + bK) * 2;
    const uint32_t bW2To = smb + F_W2T * 4 + ((48 + bORow) * WKS + bK) * 2;
    const uint32_t bW3S  = smb + F_W3S * 4 + ((nb3 + bRow) * WKS + bK) * 2;
    const uint32_t bW3T  = smb + F_W3T * 4 + ((nb3 + bRow) * WKS + bK) * 2;
    const uint32_t bW1S  = smb + F_W1S0 * 4 + ((nb2 + bRow) * W1KS + bK) * 2;
    const uint32_t bW1So = smb + F_W1S0 * 4 + ((48 + bORow) * W1KS + bK) * 2;
    const uint32_t bW1T  = smb + F_W1T0 * 4 + ((nb2 + bRow) * W1KS + bK) * 2;
    const uint32_t bW1To = smb + F_W1T0 * 4 + ((48 + bORow) * W1KS + bK) * 2;

    float accS[7][4], accT[7][4];
#pragma unroll
    for (int b = 0; b < 7; b++)
#pragma unroll
        for (int q = 0; q < 4; q++) { accS[b][q] = 0.f; accT[b][q] = 0.f; }
    float ldacc[2] = {0.f, 0.f};

    __syncthreads();

    // ---- STEP 0: constants precomputed; epilogue only ----
    {
        float2 eV[8];
#pragma unroll
        for (int nt = 0; nt < 4; nt++) {
            eV[nt * 2 + 0] = __ldcs((const float2*)&eR0[nt * 8]);
            eV[nt * 2 + 1] = __ldcs((const float2*)&eR1[nt * 8]);
        }
        float partial = 0.f;
#pragma unroll
        for (int nt = 0; nt < 4; nt++) {
            int cc = nb3 + nt * 8 + 2 * t;
            float s0a = smf[FC_S0 + cc],        s0b = smf[FC_S0 + cc + 1];
            float t0a = smf[FC_S0 + 64 + cc],   t0b = smf[FC_S0 + 64 + cc + 1];
            float exa = smf[FC_S0 + 128 + cc],  exb = smf[FC_S0 + 128 + cc + 1];
            partial += s0a + s0b;
#pragma unroll
            for (int h = 0; h < 2; h++) {
                int row = mrow + h * 8 + g;
                float2 e2 = eV[nt * 2 + h];
                float z0 = exa * e2.x + t0a;
                float z1 = exb * e2.y + t0b;
                float* zp = (h == 0) ? (zR0 + nt * 8) : (zR1 + nt * 8);
                __stcs((float2*)zp, make_float2(z0, z1));
                __nv_bfloat162 zb = __floats2bfloat162_rn(z0, z1);
                smu[F_ZB + row * 36 + (cc >> 1)] = *(uint32_t*)&zb;
            }
        }
        ldacc[0] += partial;
        ldacc[1] += partial;
    }
    __syncthreads();

    for (int i = 1; i < DIMS; i++) {
        const uint32_t rOff = (uint32_t)(((i + 1) & 1) * (SLICE_W * 4));  // read parity (bytes)

        if (nw == 0)
            gemm_dual<4, 7, W1KS>(aZB, bW1S + rOff, bW1So + rOff,
                                  bW1T + rOff, bW1To + rOff, accS, accT);
        else
            gemm_dual<4, 6, W1KS>(aZB, bW1S + rOff, 0, bW1T + rOff, 0, accS, accT);
        if (nw == 0) store_h<7>(accS, smf + F_B1S, smu + F_HB1, nb2, mrow, g, t);
        else         store_h<6>(accS, smf + F_B1S, smu + F_HB1, nb2, mrow, g, t);
        bar_n(pairBar, 64);

        if (nw == 0) {
            float D[7][4] = {};
            gemm1m<7, 7, WKS>(aHB1, bW2S, bW2So, D);
            store_h<7>(D, smf + F_B2S, smu + F_HB2, nb2, mrow, g, t);
        } else {
            float D[6][4] = {};
            gemm1m<7, 6, WKS>(aHB1, bW2S, 0, D);
            store_h<6>(D, smf + F_B2S, smu + F_HB2, nb2, mrow, g, t);
        }
        bar_n(pairBar, 64);

        float sv[4][4];
        {
            float Ds[4][4] = {};
            gemm1m<7, 4, WKS>(aHB2, bW3S, 0, Ds);
#pragma unroll
            for (int nt = 0; nt < 4; nt++) {
                int cc = nb3 + nt * 8 + 2 * t;
                float2 b3 = *(const float2*)&smf[F_B3S + cc];
#pragma unroll
                for (int h = 0; h < 2; h++) {
                    float v0 = sigm(Ds[nt][2 * h + 0] + b3.x);
                    float v1 = sigm(Ds[nt][2 * h + 1] + b3.y);
                    sv[nt][2 * h + 0] = v0;
                    sv[nt][2 * h + 1] = v1;
                    ldacc[h] += v0 + v1;
                }
            }
            if (nw == 0) store_h<7>(accT, smf + F_B1T, smu + F_HB1, nb2, mrow, g, t);
            else         store_h<6>(accT, smf + F_B1T, smu + F_HB1, nb2, mrow, g, t);
        }
        bar_n(pairBar, 64);

        {
            uint4 w1v[2];
            if (i < DIMS - 1)
                loadSlice((const uint4*)(g_scratch + GS_W1 + i * SLICE_W), w1v, tid);
            prefetchL2(eR0 + i * KD);
            prefetchL2(eR1 + i * KD);
            if (nw == 0) {
                float D[7][4] = {};
                gemm1m<7, 7, WKS>(aHB1, bW2T, bW2To, D);
                store_h<7>(D, smf + F_B2T, smu + F_HB2, nb2, mrow, g, t);
            } else {
                float D[6][4] = {};
                gemm1m<7, 6, WKS>(aHB1, bW2T, 0, D);
                store_h<6>(D, smf + F_B2T, smu + F_HB2, nb2, mrow, g, t);
            }
            if (i < DIMS - 1)
                storeSlice((uint4*)(smf + F_W1S0) + (i & 1) * SLICE_V, w1v, tid);
        }
        bar_n(pairBar, 64);

        {
            const int eoff = i * KD;
            uint4 w1v[2];
            if (i < DIMS - 1)
                loadSlice((const uint4*)(g_scratch + GS_W1 + (7 + i) * SLICE_W), w1v, tid);
            float2 eV[8];
#pragma unroll
            for (int nt = 0; nt < 4; nt++) {
                eV[nt * 2 + 0] = __ldcs((const float2*)&eR0[eoff + nt * 8]);
                eV[nt * 2 + 1] = __ldcs((const float2*)&eR1[eoff + nt * 8]);
            }

            float Dt[4][4] = {};
            gemm1m<7, 4, WKS>(aHB2, bW3T, 0, Dt);
#pragma unroll
            for (int nt = 0; nt < 4; nt++) {
                int cc = nb3 + nt * 8 + 2 * t;
                float2 b3 = *(const float2*)&smf[F_B3T + cc];
#pragma unroll
                for (int h = 0; h < 2; h++) {
                    int row = mrow + h * 8 + g;
                    float t0 = sigm(Dt[nt][2 * h + 0] + b3.x);
                    float t1 = sigm(Dt[nt][2 * h + 1] + b3.y);
                    float2 e2 = eV[nt * 2 + h];
                    float z0 = __expf(sv[nt][2 * h + 0]) * e2.x + t0;
                    float z1 = __expf(sv[nt][2 * h + 1]) * e2.y + t1;
                    float* zp = (h == 0) ? (zR0 + eoff + nt * 8) : (zR1 + eoff + nt * 8);
                    __stcs((float2*)zp, make_float2(z0, z1));
                    if (i < DIMS - 1) {
                        __nv_bfloat162 zb = __floats2bfloat162_rn(z0, z1);
                        smu[F_ZB + row * 36 + (cc >> 1)] = *(uint32_t*)&zb;
                    }
                }
            }
            if (i < DIMS - 1)
                storeSlice((uint4*)(smf + F_W1T0) + (i & 1) * SLICE_V, w1v, tid);
        }
        __syncthreads();
    }

#pragma unroll
    for (int h = 0; h < 2; h++) {
        int row = mrow + h * 8 + g;
        smf[F_LDP + row * 8 + nw * 4 + t] = ldacc[h];
    }
    __syncthreads();
    if (tid < F_TB) {
        float v = 0.f;
#pragma unroll
        for (int q = 0; q < 8; q++) v += smf[F_LDP + tid * 8 + q];
        ldout[rowBase + tid] = v;
    }
}

// ============================================================================
// Body 2: TB=64, 3-phase quad-barrier schedule — tail CTAs
// ============================================================================
__device__ void body64(
    float* smf, long rowBase,
    const float* __restrict__ e,
    const float* __restrict__ sb1, const float* __restrict__ sb2, const float* __restrict__ sb3,
    const float* __restrict__ tb1, const float* __restrict__ tb2, const float* __restrict__ tb3,
    float* __restrict__ zout, float* __restrict__ ldout)
{
    uint32_t* smu = (uint32_t*)smf;

    const int tid = threadIdx.x;
    const int lane = tid & 31, wid = tid >> 5;
    const int g = lane >> 2, t = lane & 3;
    const int mw = wid & 3, nq = wid >> 2;
    const int mrow = mw * 16;
    const int nb2 = (nq == 0) ? 0 : (8 + 24 * nq);
    const int nb3 = nq * 16;
    const int quadBar = 1 + mw;

    const float* eR0 = e    + (rowBase + mrow + g)     * TOT + nb3 + 2 * t;
    const float* eR1 = e    + (rowBase + mrow + 8 + g) * TOT + nb3 + 2 * t;
    float*       zR0 = zout + (rowBase + mrow + g)     * TOT + nb3 + 2 * t;
    float*       zR1 = zout + (rowBase + mrow + 8 + g) * TOT + nb3 + 2 * t;

    {
        const uint4* gsv = (const uint4*)g_scratch;
        uint4* smv = (uint4*)smf;
        for (int w = tid; w < STATIC_W / 4; w += NTH) smv[w] = gsv[w];
        const uint4 z4 = make_uint4(0, 0, 0, 0);
        for (int w = tid; w < (S_B1S - S_H1S) / 4; w += NTH) smv[STATIC_W / 4 + w] = z4;
    }
    for (int idx = tid; idx < NPADK; idx += NTH) {
        smf[S_B1S + idx] = (idx < NH) ? sb1[idx] : 0.f;
        smf[S_B2S + idx] = (idx < NH) ? sb2[idx] : 0.f;
        smf[S_B1T + idx] = (idx < NH) ? tb1[idx] : 0.f;
        smf[S_B2T + idx] = (idx < NH) ? tb2[idx] : 0.f;
    }
    for (int idx = tid; idx < KD; idx += NTH) {
        smf[S_B3S + idx] = sb3[idx];
        smf[S_B3T + idx] = tb3[idx];
    }
    __syncthreads();
    if (tid < 192) smf[SC_S0 + tid] = g_scratch[GS_CONST + tid];

    const uint32_t smb = sm_u32(smf);
    const int aRow = lane & 15, aK = (lane >> 4) << 3;
    const uint32_t aH1S = smb + S_H1S * 4 + ((mrow + aRow) * WKS + aK) * 2;
    const uint32_t aH1T = smb + S_H1T * 4 + ((mrow + aRow) * WKS + aK) * 2;
    const uint32_t aH2S = smb + S_H2S * 4 + ((mrow + aRow) * WKS + aK) * 2;
    const uint32_t aH2T = smb + S_H2T * 4 + ((mrow + aRow) * WKS + aK) * 2;
    const uint32_t aZB  = smb + S_ZB * 4 + ((mrow + aRow) * ZBS + aK) * 2;
    const int bRow  = (lane & 7) + ((lane >> 4) << 3);
    const int bK    = ((lane >> 3) & 1) << 3;
    const int bORow = lane & 7;
    const uint32_t bW2S  = smb + F_W2S * 4 + ((nb2 + bRow) * WKS + bK) * 2;
    const uint32_t bW2So = smb + F_W2S * 4 + ((nb2 + 16 + bORow) * WKS + bK) * 2;
    const uint32_t bW2T  = smb + F_W2T * 4 + ((nb2 + bRow) * WKS + bK) * 2;
    const uint32_t bW2To = smb + F_W2T * 4 + ((nb2 + 16 + bORow) * WKS + bK) * 2;
    const uint32_t bW3S  = smb + F_W3S * 4 + ((nb3 + bRow) * WKS + bK) * 2;
    const uint32_t bW3T  = smb + F_W3T * 4 + ((nb3 + bRow) * WKS + bK) * 2;
    const uint32_t bW1S  = smb + F_W1S0 * 4 + ((nb2 + bRow) * W1KS + bK) * 2;
    const uint32_t bW1So = smb + F_W1S0 * 4 + ((nb2 + 16 + bORow) * W1KS + bK) * 2;
    const uint32_t bW1T  = smb + F_W1T0 * 4 + ((nb2 + bRow) * W1KS + bK) * 2;
    const uint32_t bW1To = smb + F_W1T0 * 4 + ((nb2 + 16 + bORow) * W1KS + bK) * 2;

    float accS[4][4], accT[4][4];
#pragma unroll
    for (int b = 0; b < 4; b++)
#pragma unroll
        for (int q = 0; q < 4; q++) { accS[b][q] = 0.f; accT[b][q] = 0.f; }
    float ldacc[2] = {0.f, 0.f};

    __syncthreads();

    // ---- STEP 0: epilogue only ----
    {
        float2 eV[4];
#pragma unroll
        for (int nt = 0; nt < 2; nt++) {
            eV[nt * 2 + 0] = __ldcs((const float2*)&eR0[nt * 8]);
            eV[nt * 2 + 1] = __ldcs((const float2*)&eR1[nt * 8]);
        }
        float partial = 0.f;
#pragma unroll
        for (int nt = 0; nt < 2; nt++) {
            int cc = nb3 + nt * 8 + 2 * t;
            float s0a = smf[SC_S0 + cc],        s0b = smf[SC_S0 + cc + 1];
            float t0a = smf[SC_S0 + 64 + cc],   t0b = smf[SC_S0 + 64 + cc + 1];
            float exa = smf[SC_S0 + 128 + cc],  exb = smf[SC_S0 + 128 + cc + 1];
            partial += s0a + s0b;
#pragma unroll
            for (int h = 0; h < 2; h++) {
                int row = mrow + h * 8 + g;
                float2 e2 = eV[nt * 2 + h];
                float z0 = exa * e2.x + t0a;
                float z1 = exb * e2.y + t0b;
                float* zp = (h == 0) ? (zR0 + nt * 8) : (zR1 + nt * 8);
                __stcs((float2*)zp, make_float2(z0, z1));
                __nv_bfloat162 zb = __floats2bfloat162_rn(z0, z1);
                smu[S_ZB + row * 36 + (cc >> 1)] = *(uint32_t*)&zb;
            }
        }
        ldacc[0] += partial;
        ldacc[1] += partial;
    }
    __syncthreads();

    for (int i = 1; i < DIMS; i++) {
        const uint32_t rOff = (uint32_t)(((i + 1) & 1) * (SLICE_W * 4));

        if (nq == 0) {
            gemm_dual<4, 4, W1KS>(aZB, bW1S + rOff, 0, bW1T + rOff, 0, accS, accT);
            store_h<4>(accS, smf + S_B1S, smu + S_H1S, nb2, mrow, g, t);
            store_h<4>(accT, smf + S_B1T, smu + S_H1T, nb2, mrow, g, t);
        } else {
            gemm_dual<4, 3, W1KS>(aZB, bW1S + rOff, bW1So + rOff,
                                  bW1T + rOff, bW1To + rOff, accS, accT);
            store_h<3>(accS, smf + S_B1S, smu + S_H1S, nb2, mrow, g, t);
            store_h<3>(accT, smf + S_B1T, smu + S_H1T, nb2, mrow, g, t);
        }
        bar_n(quadBar, 128);

        {
            uint4 w1v[2];
            if (i < DIMS - 1)
                loadSlice((const uint4*)(g_scratch + GS_W1 + i * SLICE_W), w1v, tid);
            prefetchL2(eR0 + i * KD);
            prefetchL2(eR1 + i * KD);
            if (nq == 0) {
                float D[4][4] = {};
                gemm1m<7, 4, WKS>(aH1S, bW2S, 0, D);
                store_h<4>(D, smf + S_B2S, smu + S_H2S, nb2, mrow, g, t);
                float D2[4][4] = {};
                gemm1m<7, 4, WKS>(aH1T, bW2T, 0, D2);
                store_h<4>(D2, smf + S_B2T, smu + S_H2T, nb2, mrow, g, t);
            } else {
                float D[3][4] = {};
                gemm1m<7, 3, WKS>(aH1S, bW2S, bW2So, D);
                store_h<3>(D, smf + S_B2S, smu + S_H2S, nb2, mrow, g, t);
                float D2[3][4] = {};
                gemm1m<7, 3, WKS>(aH1T, bW2T, bW2To, D2);
                store_h<3>(D2, smf + S_B2T, smu + S_H2T, nb2, mrow, g, t);
            }
            if (i < DIMS - 1)
                storeSlice((uint4*)(smf + F_W1S0) + (i & 1) * SLICE_V, w1v, tid);
        }
        bar_n(quadBar, 128);

        {
            uint4 w1v[2];
            if (i < DIMS - 1)
                loadSlice((const uint4*)(g_scratch + GS_W1 + (7 + i) * SLICE_W), w1v, tid);

            const int eoff = i * KD;
            float2 eV[4];
#pragma unroll
            for (int nt = 0; nt < 2; nt++) {
                eV[nt * 2 + 0] = __ldcs((const float2*)&eR0[eoff + nt * 8]);
                eV[nt * 2 + 1] = __ldcs((const float2*)&eR1[eoff + nt * 8]);
            }

            float Ds[2][4] = {};
            gemm1m<7, 2, WKS>(aH2S, bW3S, 0, Ds);
            float sv[2][4];
#pragma unroll
            for (int nt = 0; nt < 2; nt++) {
                int cc = nb3 + nt * 8 + 2 * t;
                float2 b3 = *(const float2*)&smf[S_B3S + cc];
#pragma unroll
                for (int h = 0; h < 2; h++) {
                    float v0 = sigm(Ds[nt][2 * h + 0] + b3.x);
                    float v1 = sigm(Ds[nt][2 * h + 1] + b3.y);
                    sv[nt][2 * h + 0] = v0;
                    sv[nt][2 * h + 1] = v1;
                    ldacc[h] += v0 + v1;
                }
            }

            float Dt[2][4] = {};
            gemm1m<7, 2, WKS>(aH2T, bW3T, 0, Dt);
#pragma unroll
            for (int nt = 0; nt < 2; nt++) {
                int cc = nb3 + nt * 8 + 2 * t;
                float2 b3 = *(const float2*)&smf[S_B3T + cc];
#pragma unroll
                for (int h = 0; h < 2; h++) {
                    int row = mrow + h * 8 + g;
                    float t0 = sigm(Dt[nt][2 * h + 0] + b3.x);
                    float t1 = sigm(Dt[nt][2 * h + 1] + b3.y);
                    float2 e2 = eV[nt * 2 + h];
                    float z0 = __expf(sv[nt][2 * h + 0]) * e2.x + t0;
                    float z1 = __expf(sv[nt][2 * h + 1]) * e2.y + t1;
                    float* zp = (h == 0) ? (zR0 + eoff + nt * 8) : (zR1 + eoff + nt * 8);
                    __stcs((float2*)zp, make_float2(z0, z1));
                    if (i < DIMS - 1) {
                        __nv_bfloat162 zb = __floats2bfloat162_rn(z0, z1);
                        smu[S_ZB + row * 36 + (cc >> 1)] = *(uint32_t*)&zb;
                    }
                }
            }
            if (i < DIMS - 1)
                storeSlice((uint4*)(smf + F_W1T0) + (i & 1) * SLICE_V, w1v, tid);
        }
        __syncthreads();
    }

#pragma unroll
    for (int h = 0; h < 2; h++) {
        int row = mrow + h * 8 + g;
        smf[S_LDP + row * 16 + nq * 4 + t] = ldacc[h];
    }
    __syncthreads();
    if (tid < S_TB) {
        float v = 0.f;
#pragma unroll
        for (int q = 0; q < 16; q++) v += smf[S_LDP + tid * 16 + q];
        ldout[rowBase + tid] = v;
    }
}

__global__ void __launch_bounds__(NTH, 1) flow_hetero(
    const float* __restrict__ e,
    const float* __restrict__ sb1, const float* __restrict__ sb2, const float* __restrict__ sb3,
    const float* __restrict__ tb1, const float* __restrict__ tb2, const float* __restrict__ tb3,
    float* __restrict__ zout, float* __restrict__ ldout, int n1)
{
    extern __shared__ float smf[];
    const int bid = blockIdx.x;
    if (bid < n1) {
        body128(smf, (long)bid * F_TB, e, sb1, sb2, sb3, tb1, tb2, tb3, zout, ldout);
    } else {
        long rowBase = (long)n1 * F_TB + (long)(bid - n1) * S_TB;
        body64(smf, rowBase, e, sb1, sb2, sb3, tb1, tb2, tb3, zout, ldout);
    }
}

extern "C" void kernel_launch(void* const* d_in, const int* in_sizes, int n_in,
                              void* d_out, int out_size) {
    const float* e   = (const float*)d_in[0];
    // d_in[1] = C (strictly upper-triangular DAG -> incremental layer-1 acc is exact)
    const float* sW1 = (const float*)d_in[2];
    const float* sb1 = (const float*)d_in[3];
    const float* sW2 = (const float*)d_in[4];
    const float* sb2 = (const float*)d_in[5];
    const float* sW3 = (const float*)d_in[6];
    const float* sb3 = (const float*)d_in[7];
    const float* tW1 = (const float*)d_in[8];
    const float* tb1 = (const float*)d_in[9];
    const float* tW2 = (const float*)d_in[10];
    const float* tb2 = (const float*)d_in[11];
    const float* tW3 = (const float*)d_in[12];
    const float* tb3 = (const float*)d_in[13];

    float* out = (float*)d_out;
    const int B = in_sizes[0] / TOT;
    float* zout  = out;
    float* ldout = out + (size_t)B * TOT;

    const int SMS = 148;
    int tiles128 = B / 128;
    int n1 = (tiles128 / SMS) * SMS;
    long rows1 = (long)n1 * 128;
    long rem = (long)B - rows1;
    int n2 = (int)(rem / 64);
    if (rem % 64 != 0) { n1 = tiles128; rows1 = (long)n1 * 128; n2 = 0; }

    init_scratch<<<33, 256>>>(sW1, sb1, sW2, sb2, sW3, sb3,
                              tW1, tb1, tW2, tb2, tW3, tb3);

    cudaFuncSetAttribute(flow_hetero, cudaFuncAttributeMaxDynamicSharedMemorySize,
                         F_SMW * (int)sizeof(float));

    flow_hetero<<<n1 + n2, NTH, F_SMW * sizeof(float)>>>(
        e, sb1, sb2, sb3, tb1, tb2, tb3, zout, ldout, n1);
}